// round 3
// baseline (speedup 1.0000x reference)
#include <cuda_runtime.h>
#include <cstddef>
#include <cstdint>

#define B 16
#define S 1024
#define D 384
#define QK 64

__device__ float g_Q[(size_t)B * S * QK];
__device__ float g_K[(size_t)B * S * QK];
__device__ float g_Kt[(size_t)B * QK * S];   // [b][d][m]

#define CP_ASYNC16(dst_u32, src_ptr) \
    asm volatile("cp.async.cg.shared.global [%0], [%1], 16;\n" :: "r"(dst_u32), "l"(src_ptr))
#define CP_COMMIT() asm volatile("cp.async.commit_group;\n" ::)
#define CP_WAIT1()  asm volatile("cp.async.wait_group 1;\n" ::)
#define CP_WAIT0()  asm volatile("cp.async.wait_group 0;\n" ::)

// ---------------------------------------------------------------------------
// Kernel 1: per-position Q/K projection (memory-bound on the 200MB weights).
// ---------------------------------------------------------------------------
__global__ __launch_bounds__(256) void proj_kernel(
    const float* __restrict__ x, const float* __restrict__ qw,
    const float* __restrict__ qb, const float* __restrict__ kw)
{
    const int n = blockIdx.x;
    __shared__ float xs[B][D + 1];

    const int tid = threadIdx.x;
    for (int idx = tid; idx < B * D; idx += 256) {
        int b = idx / D, c = idx % D;
        xs[b][c] = x[((size_t)b * S + n) * D + c];
    }
    __syncthreads();

    const int lane = tid & 31;
    const int wid  = tid >> 5;
    const int b    = lane & 15;
    const int half = lane >> 4;
    const float scale = 0.05103103630798287f;  // 384^-0.5

    #pragma unroll
    for (int s = 0; s < 8; s++) {
        const int gidx = (wid * 8 + s) * 2 + half;
        const bool isq = (gidx < 64);
        const int d = isq ? gidx : gidx - 64;
        const float* w = isq ? qw : kw;
        const float4* wp = (const float4*)(w + ((size_t)n * QK + d) * D);

        float a0 = 0.f, a1 = 0.f, a2 = 0.f, a3 = 0.f;
        #pragma unroll 8
        for (int c4 = 0; c4 < D / 4; c4++) {
            float4 wv = __ldg(wp + c4);
            int c = c4 * 4;
            a0 += xs[b][c + 0] * wv.x;
            a1 += xs[b][c + 1] * wv.y;
            a2 += xs[b][c + 2] * wv.z;
            a3 += xs[b][c + 3] * wv.w;
        }
        float acc = (a0 + a1) + (a2 + a3);

        if (isq) g_Q[((size_t)b * S + n) * QK + d] = scale * (acc + qb[n * QK + d]);
        else     g_K[((size_t)b * S + n) * QK + d] = acc;
    }
}

// ---------------------------------------------------------------------------
// Kernel 1b: transpose K -> Kt[b][d][m]
// ---------------------------------------------------------------------------
__global__ __launch_bounds__(256) void transpose_k_kernel()
{
    __shared__ float tb[32][33];
    const int b = blockIdx.z, m0 = blockIdx.x * 32, d0 = blockIdx.y * 32;
    const int tx = threadIdx.x, ty = threadIdx.y;

    #pragma unroll
    for (int j = 0; j < 4; j++)
        tb[ty + 8 * j][tx] = g_K[((size_t)b * S + m0 + ty + 8 * j) * QK + d0 + tx];
    __syncthreads();
    #pragma unroll
    for (int j = 0; j < 4; j++)
        g_Kt[((size_t)b * QK + d0 + ty + 8 * j) * S + m0 + tx] = tb[tx][ty + 8 * j];
}

// ---------------------------------------------------------------------------
// Kernel 2: logits = Q @ Kt + bias. 128x128 tile, K=64 resident, 8x8 micro.
//   Qs[r][k] row-major pitch 68 (scalar broadcast reads)
//   Ks[k][m] k-major   pitch 132 (float4 reads, conflict-free)
// dyn smem = (128*68 + 64*132)*4 = 68608 B
// ---------------------------------------------------------------------------
__global__ __launch_bounds__(256) void logits_kernel2(
    const float* __restrict__ attn_bias, float* __restrict__ attn)
{
    extern __shared__ float sm[];
    float* Qs = sm;            // 128 x 68
    float* Ks = sm + 128 * 68; // 64 x 132

    const int b  = blockIdx.z;
    const int n0 = blockIdx.y * 128;
    const int m0 = blockIdx.x * 128;
    const int tid = threadIdx.x;

    #pragma unroll
    for (int i = 0; i < 8; i++) {
        int g = tid + 256 * i;
        int r = g >> 4, q = g & 15;                       // Q: 128 rows x 16 f4
        *(float4*)&Qs[r * 68 + 4 * q] =
            *(const float4*)&g_Q[((size_t)b * S + n0 + r) * QK + 4 * q];
    }
    #pragma unroll
    for (int i = 0; i < 8; i++) {
        int g = tid + 256 * i;
        int r = g >> 5, c = g & 31;                       // Kt: 64 rows x 32 f4
        *(float4*)&Ks[r * 132 + 4 * c] =
            *(const float4*)&g_Kt[((size_t)b * QK + r) * S + m0 + 4 * c];
    }
    __syncthreads();

    const int tx = tid & 15, ty = tid >> 4;
    const int tx4 = tx * 4, ty4 = ty * 4;

    const float* ar[8];
    #pragma unroll
    for (int i = 0; i < 4; i++) {
        ar[i]     = Qs + (ty4 + i) * 68;
        ar[4 + i] = Qs + (64 + ty4 + i) * 68;
    }

    float acc[8][8] = {};
    #pragma unroll 8
    for (int k = 0; k < QK; k++) {
        float a[8];
        #pragma unroll
        for (int i = 0; i < 8; i++) a[i] = ar[i][k];
        float4 b0 = *(const float4*)&Ks[k * 132 + tx4];
        float4 b1 = *(const float4*)&Ks[k * 132 + 64 + tx4];
        float bv[8] = {b0.x, b0.y, b0.z, b0.w, b1.x, b1.y, b1.z, b1.w};
        #pragma unroll
        for (int i = 0; i < 8; i++)
            #pragma unroll
            for (int j = 0; j < 8; j++)
                acc[i][j] += a[i] * bv[j];
    }

    #pragma unroll
    for (int i = 0; i < 8; i++) {
        const int row = n0 + ((i < 4) ? (ty4 + i) : (64 + ty4 + i - 4));
        float4 bb0 = *(const float4*)&attn_bias[(size_t)row * S + m0 + tx4];
        float4 bb1 = *(const float4*)&attn_bias[(size_t)row * S + m0 + 64 + tx4];
        float4 v0 = {acc[i][0] + bb0.x, acc[i][1] + bb0.y, acc[i][2] + bb0.z, acc[i][3] + bb0.w};
        float4 v1 = {acc[i][4] + bb1.x, acc[i][5] + bb1.y, acc[i][6] + bb1.z, acc[i][7] + bb1.w};
        *(float4*)&attn[((size_t)b * S + row) * S + m0 + tx4]      = v0;
        *(float4*)&attn[((size_t)b * S + row) * S + m0 + 64 + tx4] = v1;
    }
}

// ---------------------------------------------------------------------------
// Kernel 3: in-place row softmax
// ---------------------------------------------------------------------------
__global__ __launch_bounds__(256) void softmax_kernel(float* __restrict__ attn)
{
    float4* p = (float4*)(attn + (size_t)blockIdx.x * S);
    const int tid = threadIdx.x;
    const int lane = tid & 31, w = tid >> 5;

    float4 v = p[tid];
    float m = fmaxf(fmaxf(v.x, v.y), fmaxf(v.z, v.w));
    #pragma unroll
    for (int o = 16; o > 0; o >>= 1) m = fmaxf(m, __shfl_xor_sync(0xffffffffu, m, o));

    __shared__ float redm[8];
    __shared__ float reds[8];
    if (lane == 0) redm[w] = m;
    __syncthreads();
    m = redm[0];
    #pragma unroll
    for (int i = 1; i < 8; i++) m = fmaxf(m, redm[i]);

    float e0 = __expf(v.x - m), e1 = __expf(v.y - m);
    float e2 = __expf(v.z - m), e3 = __expf(v.w - m);
    float ssum = (e0 + e1) + (e2 + e3);
    #pragma unroll
    for (int o = 16; o > 0; o >>= 1) ssum += __shfl_xor_sync(0xffffffffu, ssum, o);
    if (lane == 0) reds[w] = ssum;
    __syncthreads();
    ssum = reds[0];
    #pragma unroll
    for (int i = 1; i < 8; i++) ssum += reds[i];

    const float inv = 1.0f / ssum;
    float4 o4 = {e0 * inv, e1 * inv, e2 * inv, e3 * inv};
    p[tid] = o4;
}

// ---------------------------------------------------------------------------
// Kernel 4: out = attn @ x. Persistent (grid=148), 128x128 tiles, KT=32,
// cp.async double-buffered, 8x8 microtile.
//   As[r][k] row-major pitch 36  (natural attn layout; scalar broadcast reads)
//   Xs[k][c] k-major   pitch 132 (natural x layout;  float4 reads)
// dyn smem = 2*(128*36 + 32*132)*4 = 70656 B
// ---------------------------------------------------------------------------
#define OUT_BUF_F 8832   // floats per buffer (4608 + 4224)

__global__ __launch_bounds__(256) void out_kernel2(
    const float* __restrict__ x, const float* __restrict__ attn,
    float* __restrict__ out)
{
    extern __shared__ float sm[];
    const int tid = threadIdx.x;
    const int tx = tid & 15, ty = tid >> 4;
    const int tx4 = tx * 4, ty4 = ty * 4;

    // per-thread load descriptors (constant across tiles)
    // A tile: 128 rows x 32 cols = 1024 float4  -> 4 per thread
    int aRow[4], aCol[4];
    #pragma unroll
    for (int i = 0; i < 4; i++) { int g = tid + 256 * i; aRow[i] = g >> 3; aCol[i] = (g & 7) * 4; }
    // X tile: 32 rows x 128 cols = 1024 float4  -> 4 per thread  (R2 bug: was 2)
    int xRow[4], xCol[4];
    #pragma unroll
    for (int i = 0; i < 4; i++) { int g = tid + 256 * i; xRow[i] = g >> 5; xCol[i] = (g & 31) * 4; }

    const uint32_t smBase = (uint32_t)__cvta_generic_to_shared(sm);

    for (int t = blockIdx.x; t < 384; t += 148) {
        const int b  = t / 24;
        const int r2 = t % 24;
        const int n0 = (r2 / 3) * 128;
        const int c0 = (r2 % 3) * 128;

        const float* aBase = attn + ((size_t)b * S + n0) * (size_t)S;  // + r*S + m
        const float* xBase = x + (size_t)b * S * D + c0;               // + m*D + c

        float acc[8][8] = {};

        // ---- prefetch k-tile 0 into buffer 0 ----
        {
            const uint32_t aD = smBase;
            const uint32_t xD = smBase + 4608u * 4u;
            #pragma unroll
            for (int i = 0; i < 4; i++)
                CP_ASYNC16(aD + (uint32_t)(aRow[i] * 36 + aCol[i]) * 4u,
                           aBase + (size_t)aRow[i] * S + aCol[i]);
            #pragma unroll
            for (int i = 0; i < 4; i++)
                CP_ASYNC16(xD + (uint32_t)(xRow[i] * 132 + xCol[i]) * 4u,
                           xBase + (size_t)xRow[i] * D + xCol[i]);
            CP_COMMIT();
        }

        for (int kt = 0; kt < 32; kt++) {
            const int cur = kt & 1;
            if (kt < 31) {
                const int m1 = (kt + 1) * 32;
                const uint32_t bufOff = (uint32_t)((cur ^ 1) * OUT_BUF_F) * 4u;
                const uint32_t aD = smBase + bufOff;
                const uint32_t xD = smBase + bufOff + 4608u * 4u;
                #pragma unroll
                for (int i = 0; i < 4; i++)
                    CP_ASYNC16(aD + (uint32_t)(aRow[i] * 36 + aCol[i]) * 4u,
                               aBase + (size_t)aRow[i] * S + m1 + aCol[i]);
                #pragma unroll
                for (int i = 0; i < 4; i++)
                    CP_ASYNC16(xD + (uint32_t)(xRow[i] * 132 + xCol[i]) * 4u,
                               xBase + (size_t)(m1 + xRow[i]) * D + xCol[i]);
                CP_COMMIT();
                CP_WAIT1();
            } else {
                CP_WAIT0();
            }
            __syncthreads();

            const float* A = sm + cur * OUT_BUF_F;           // [128][36]
            const float* X = sm + cur * OUT_BUF_F + 4608;    // [32][132]
            const float* ar[8];
            #pragma unroll
            for (int i = 0; i < 4; i++) {
                ar[i]     = A + (ty4 + i) * 36;
                ar[4 + i] = A + (64 + ty4 + i) * 36;
            }

            #pragma unroll 8
            for (int k = 0; k < 32; k++) {
                float a[8];
                #pragma unroll
                for (int i = 0; i < 8; i++) a[i] = ar[i][k];
                float4 b0 = *(const float4*)&X[k * 132 + tx4];
                float4 b1 = *(const float4*)&X[k * 132 + 64 + tx4];
                float bv[8] = {b0.x, b0.y, b0.z, b0.w, b1.x, b1.y, b1.z, b1.w};
                #pragma unroll
                for (int i = 0; i < 8; i++)
                    #pragma unroll
                    for (int j = 0; j < 8; j++)
                        acc[i][j] += a[i] * bv[j];
            }
            __syncthreads();
        }

        // ---- store 128x128 tile ----
        #pragma unroll
        for (int i = 0; i < 8; i++) {
            const int row = n0 + ((i < 4) ? (ty4 + i) : (64 + ty4 + i - 4));
            float4 v0 = {acc[i][0], acc[i][1], acc[i][2], acc[i][3]};
            float4 v1 = {acc[i][4], acc[i][5], acc[i][6], acc[i][7]};
            *(float4*)&out[((size_t)b * S + row) * D + c0 + tx4]      = v0;
            *(float4*)&out[((size_t)b * S + row) * D + c0 + 64 + tx4] = v1;
        }
    }
}

// ---------------------------------------------------------------------------
extern "C" void kernel_launch(void* const* d_in, const int* in_sizes, int n_in,
                              void* d_out, int out_size)
{
    const float* x         = (const float*)d_in[0];
    const float* q_weight  = (const float*)d_in[1];
    const float* q_bias    = (const float*)d_in[2];
    const float* k_weight  = (const float*)d_in[3];
    const float* attn_bias = (const float*)d_in[4];

    float* out  = (float*)d_out;                       // [B,S,D]
    float* attn = (float*)d_out + (size_t)B * S * D;   // [B,S,S]

    cudaFuncSetAttribute(logits_kernel2, cudaFuncAttributeMaxDynamicSharedMemorySize, 68608);
    cudaFuncSetAttribute(out_kernel2,    cudaFuncAttributeMaxDynamicSharedMemorySize, 70656);

    proj_kernel<<<S, 256>>>(x, q_weight, q_bias, k_weight);

    transpose_k_kernel<<<dim3(32, 2, 16), dim3(32, 8)>>>();

    logits_kernel2<<<dim3(8, 8, 16), 256, 68608>>>(attn_bias, attn);

    softmax_kernel<<<B * S, 256>>>(attn);

    out_kernel2<<<148, 256, 70656>>>(x, attn, out);
}

// round 5
// speedup vs baseline: 2.3824x; 2.3824x over previous
#include <cuda_runtime.h>
#include <cuda_bf16.h>
#include <mma.h>
#include <cstddef>
#include <cstdint>

using namespace nvcuda;

#define B 16
#define S 1024
#define D 384
#define QK 64

// bf16 hi/lo split operands
__device__ __nv_bfloat16 g_Qhi[(size_t)B * S * QK];
__device__ __nv_bfloat16 g_Qlo[(size_t)B * S * QK];
__device__ __nv_bfloat16 g_Khi[(size_t)B * S * QK];
__device__ __nv_bfloat16 g_Klo[(size_t)B * S * QK];
__device__ __nv_bfloat16 g_XThi[(size_t)B * D * S];   // [b][c][m]
__device__ __nv_bfloat16 g_XTlo[(size_t)B * D * S];
__device__ __nv_bfloat16 g_Phi[(size_t)B * S * S];    // softmax probs hi
__device__ __nv_bfloat16 g_Plo[(size_t)B * S * S];

#define CP_ASYNC16(dst_u32, src_ptr) \
    asm volatile("cp.async.cg.shared.global [%0], [%1], 16;\n" :: "r"(dst_u32), "l"(src_ptr))
#define CP_COMMIT() asm volatile("cp.async.commit_group;\n" ::)
#define CP_WAIT1()  asm volatile("cp.async.wait_group 1;\n" ::)
#define CP_WAIT0()  asm volatile("cp.async.wait_group 0;\n" ::)

// smem tile geometry: 128 rows x 64 bf16, pitch 72 bf16 (144B).
// 144B row stride => ldmatrix rows hit distinct bank groups (gcd(36,32)=4).
#define PITCH 72
#define MAT_BYTES (128 * PITCH * 2)   // 18432

typedef wmma::fragment<wmma::matrix_a, 16, 16, 16, __nv_bfloat16, wmma::row_major> FragA;
typedef wmma::fragment<wmma::matrix_b, 16, 16, 16, __nv_bfloat16, wmma::col_major> FragB;
typedef wmma::fragment<wmma::accumulator, 16, 16, 16, float> FragC;

// ---------------------------------------------------------------------------
// Kernel 1: per-position Q/K projection -> bf16 hi/lo
// ---------------------------------------------------------------------------
__global__ __launch_bounds__(256) void proj_kernel(
    const float* __restrict__ x, const float* __restrict__ qw,
    const float* __restrict__ qb, const float* __restrict__ kw)
{
    const int n = blockIdx.x;
    __shared__ float xs[B][D + 1];

    const int tid = threadIdx.x;
    for (int idx = tid; idx < B * D; idx += 256) {
        int b = idx / D, c = idx % D;
        xs[b][c] = x[((size_t)b * S + n) * D + c];
    }
    __syncthreads();

    const int lane = tid & 31;
    const int wid  = tid >> 5;
    const int b    = lane & 15;
    const int half = lane >> 4;
    const float scale = 0.05103103630798287f;  // 384^-0.5

    #pragma unroll
    for (int s = 0; s < 8; s++) {
        const int gidx = (wid * 8 + s) * 2 + half;
        const bool isq = (gidx < 64);
        const int d = isq ? gidx : gidx - 64;
        const float* w = isq ? qw : kw;
        const float4* wp = (const float4*)(w + ((size_t)n * QK + d) * D);

        float a0 = 0.f, a1 = 0.f, a2 = 0.f, a3 = 0.f;
        #pragma unroll 8
        for (int c4 = 0; c4 < D / 4; c4++) {
            float4 wv = __ldg(wp + c4);
            int c = c4 * 4;
            a0 += xs[b][c + 0] * wv.x;
            a1 += xs[b][c + 1] * wv.y;
            a2 += xs[b][c + 2] * wv.z;
            a3 += xs[b][c + 3] * wv.w;
        }
        float acc = (a0 + a1) + (a2 + a3);

        const size_t o = ((size_t)b * S + n) * QK + d;
        if (isq) {
            float qv = scale * (acc + qb[n * QK + d]);
            __nv_bfloat16 h = __float2bfloat16(qv);
            g_Qhi[o] = h;
            g_Qlo[o] = __float2bfloat16(qv - __bfloat162float(h));
        } else {
            __nv_bfloat16 h = __float2bfloat16(acc);
            g_Khi[o] = h;
            g_Klo[o] = __float2bfloat16(acc - __bfloat162float(h));
        }
    }
}

// ---------------------------------------------------------------------------
// Kernel 1b: transpose+split x -> XT[b][c][m] bf16 hi/lo
// ---------------------------------------------------------------------------
__global__ __launch_bounds__(256) void xsplit_kernel(const float* __restrict__ x)
{
    __shared__ float tb[32][33];
    const int b = blockIdx.z, m0 = blockIdx.x * 32, c0 = blockIdx.y * 32;
    const int tx = threadIdx.x, ty = threadIdx.y;

    #pragma unroll
    for (int j = 0; j < 4; j++)
        tb[ty + 8 * j][tx] = x[((size_t)b * S + m0 + ty + 8 * j) * D + c0 + tx];
    __syncthreads();
    #pragma unroll
    for (int j = 0; j < 4; j++) {
        float v = tb[tx][ty + 8 * j];   // = x[m0+tx][c0+ty+8j]
        size_t o = ((size_t)b * D + c0 + ty + 8 * j) * S + m0 + tx;
        __nv_bfloat16 h = __float2bfloat16(v);
        g_XThi[o] = h;
        g_XTlo[o] = __float2bfloat16(v - __bfloat162float(h));
    }
}

// ---------------------------------------------------------------------------
// Kernel 2: logits = Q @ K^T + bias via wmma bf16 hi/lo.
// 128x128 tile, K=64 resident. 8 warps: warp tile 64(n) x 32(m).
// dyn smem = 4 * 18432 = 73728
// ---------------------------------------------------------------------------
__global__ __launch_bounds__(256) void logits_mma(
    const float* __restrict__ attn_bias, float* __restrict__ attn)
{
    extern __shared__ __nv_bfloat16 sm[];
    __nv_bfloat16* Qh = sm;                 // [128][72]
    __nv_bfloat16* Ql = sm + 128 * PITCH;
    __nv_bfloat16* Kh = sm + 2 * 128 * PITCH;
    __nv_bfloat16* Kl = sm + 3 * 128 * PITCH;

    const int tid = threadIdx.x;
    const int bx = blockIdx.x;
    const int mt = bx & 7, nt = (bx >> 3) & 7, b = bx >> 6;
    const int n0 = nt * 128, m0 = mt * 128;

    const uint32_t smb = (uint32_t)__cvta_generic_to_shared(sm);
    const __nv_bfloat16* srcs[4] = {
        g_Qhi + ((size_t)b * S + n0) * QK, g_Qlo + ((size_t)b * S + n0) * QK,
        g_Khi + ((size_t)b * S + m0) * QK, g_Klo + ((size_t)b * S + m0) * QK };

    #pragma unroll
    for (int mtx = 0; mtx < 4; mtx++) {
        const __nv_bfloat16* src = srcs[mtx];
        const uint32_t dst = smb + (uint32_t)mtx * MAT_BYTES;
        #pragma unroll
        for (int i = 0; i < 4; i++) {
            int g = tid + 256 * i;          // 1024 chunks: 128 rows x 8 x 16B
            int r = g >> 3, c16 = g & 7;
            CP_ASYNC16(dst + (uint32_t)(r * 144 + c16 * 16),
                       src + (size_t)r * QK + c16 * 8);
        }
    }
    CP_COMMIT(); CP_WAIT0();
    __syncthreads();

    const int wid = tid >> 5;
    const int wn = wid >> 2;     // 0..1  -> 64-row group
    const int wm = wid & 3;      // 0..3  -> 32-col group

    FragC acc[4][2];
    #pragma unroll
    for (int i = 0; i < 4; i++)
        #pragma unroll
        for (int j = 0; j < 2; j++) wmma::fill_fragment(acc[i][j], 0.0f);

    #pragma unroll
    for (int kk = 0; kk < 4; kk++) {
        FragA ah[4], al[4];
        FragB bh[2], bl[2];
        #pragma unroll
        for (int i = 0; i < 4; i++) {
            int r = wn * 64 + i * 16;
            wmma::load_matrix_sync(ah[i], Qh + r * PITCH + kk * 16, PITCH);
            wmma::load_matrix_sync(al[i], Ql + r * PITCH + kk * 16, PITCH);
        }
        #pragma unroll
        for (int j = 0; j < 2; j++) {
            int c = wm * 32 + j * 16;
            wmma::load_matrix_sync(bh[j], Kh + c * PITCH + kk * 16, PITCH);
            wmma::load_matrix_sync(bl[j], Kl + c * PITCH + kk * 16, PITCH);
        }
        #pragma unroll
        for (int i = 0; i < 4; i++)
            #pragma unroll
            for (int j = 0; j < 2; j++) {
                wmma::mma_sync(acc[i][j], ah[i], bh[j], acc[i][j]);
                wmma::mma_sync(acc[i][j], ah[i], bl[j], acc[i][j]);
                wmma::mma_sync(acc[i][j], al[i], bh[j], acc[i][j]);
            }
    }

    #pragma unroll
    for (int i = 0; i < 4; i++) {
        const int row = n0 + wn * 64 + i * 16;
        #pragma unroll
        for (int j = 0; j < 2; j++) {
            const int col = m0 + wm * 32 + j * 16;
            FragC bias;
            wmma::load_matrix_sync(bias, attn_bias + (size_t)row * S + col, S,
                                   wmma::mem_row_major);
            #pragma unroll
            for (int e = 0; e < bias.num_elements; e++)
                acc[i][j].x[e] += bias.x[e];
            wmma::store_matrix_sync(attn + ((size_t)b * S + row) * S + col,
                                    acc[i][j], S, wmma::mem_row_major);
        }
    }
}

// ---------------------------------------------------------------------------
// Kernel 3: row softmax; writes fp32 probs + bf16 hi/lo copies
// ---------------------------------------------------------------------------
__global__ __launch_bounds__(256) void softmax_kernel(float* __restrict__ attn)
{
    const size_t rowoff = (size_t)blockIdx.x * S;
    float4* p = (float4*)(attn + rowoff);
    const int tid = threadIdx.x;
    const int lane = tid & 31, w = tid >> 5;

    float4 v = p[tid];
    float m = fmaxf(fmaxf(v.x, v.y), fmaxf(v.z, v.w));
    #pragma unroll
    for (int o = 16; o > 0; o >>= 1) m = fmaxf(m, __shfl_xor_sync(0xffffffffu, m, o));

    __shared__ float redm[8];
    __shared__ float reds[8];
    if (lane == 0) redm[w] = m;
    __syncthreads();
    m = redm[0];
    #pragma unroll
    for (int i = 1; i < 8; i++) m = fmaxf(m, redm[i]);

    float e0 = __expf(v.x - m), e1 = __expf(v.y - m);
    float e2 = __expf(v.z - m), e3 = __expf(v.w - m);
    float ssum = (e0 + e1) + (e2 + e3);
    #pragma unroll
    for (int o = 16; o > 0; o >>= 1) ssum += __shfl_xor_sync(0xffffffffu, ssum, o);
    if (lane == 0) reds[w] = ssum;
    __syncthreads();
    ssum = reds[0];
    #pragma unroll
    for (int i = 1; i < 8; i++) ssum += reds[i];

    const float inv = 1.0f / ssum;
    float v0 = e0 * inv, v1 = e1 * inv, v2 = e2 * inv, v3 = e3 * inv;
    float4 o4 = {v0, v1, v2, v3};
    p[tid] = o4;

    __nv_bfloat16 h0 = __float2bfloat16(v0), h1 = __float2bfloat16(v1);
    __nv_bfloat16 h2 = __float2bfloat16(v2), h3 = __float2bfloat16(v3);
    float l0 = v0 - __bfloat162float(h0), l1 = v1 - __bfloat162float(h1);
    float l2 = v2 - __bfloat162float(h2), l3 = v3 - __bfloat162float(h3);
    __nv_bfloat16 g0 = __float2bfloat16(l0), g1 = __float2bfloat16(l1);
    __nv_bfloat16 g2 = __float2bfloat16(l2), g3 = __float2bfloat16(l3);

    unsigned hi0 = (unsigned)__bfloat16_as_ushort(h0) | ((unsigned)__bfloat16_as_ushort(h1) << 16);
    unsigned hi1 = (unsigned)__bfloat16_as_ushort(h2) | ((unsigned)__bfloat16_as_ushort(h3) << 16);
    unsigned lo0 = (unsigned)__bfloat16_as_ushort(g0) | ((unsigned)__bfloat16_as_ushort(g1) << 16);
    unsigned lo1 = (unsigned)__bfloat16_as_ushort(g2) | ((unsigned)__bfloat16_as_ushort(g3) << 16);
    *(uint2*)&g_Phi[rowoff + (size_t)tid * 4] = make_uint2(hi0, hi1);
    *(uint2*)&g_Plo[rowoff + (size_t)tid * 4] = make_uint2(lo0, lo1);
}

// ---------------------------------------------------------------------------
// Kernel 4: out = P @ x via wmma bf16 hi/lo. 128(n)x128(c) tile,
// 16 K-chunks of 64 over m, cp.async double buffer.
// dyn smem = 2 * 4 * 18432 = 147456
// ---------------------------------------------------------------------------
__global__ __launch_bounds__(256) void out_mma(float* __restrict__ out)
{
    extern __shared__ __nv_bfloat16 sm[];

    const int tid = threadIdx.x;
    const int bx = blockIdx.x;
    const int ct = bx % 3;
    const int nt = (bx / 3) & 7;
    const int b  = bx / 24;
    const int n0 = nt * 128, c0 = ct * 128;

    const uint32_t smb = (uint32_t)__cvta_generic_to_shared(sm);
    const __nv_bfloat16* srcs[4] = {
        g_Phi  + ((size_t)b * S + n0) * S, g_Plo  + ((size_t)b * S + n0) * S,
        g_XThi + ((size_t)b * D + c0) * S, g_XTlo + ((size_t)b * D + c0) * S };

    // loader lambda-ish: chunk kc into buffer buf
    #define LOAD_CHUNK(kc, buf) do { \
        const int kof_ = (kc) * 64; \
        const uint32_t bb_ = smb + (uint32_t)(buf) * (4u * MAT_BYTES); \
        _Pragma("unroll") \
        for (int mtx = 0; mtx < 4; mtx++) { \
            const __nv_bfloat16* src = srcs[mtx] + kof_; \
            const uint32_t dst = bb_ + (uint32_t)mtx * MAT_BYTES; \
            _Pragma("unroll") \
            for (int i = 0; i < 4; i++) { \
                int g = tid + 256 * i; \
                int r = g >> 3, c16 = g & 7; \
                CP_ASYNC16(dst + (uint32_t)(r * 144 + c16 * 16), \
                           src + (size_t)r * S + c16 * 8); \
            } \
        } \
    } while (0)

    const int wid = tid >> 5;
    const int wn = wid >> 2;     // 0..1
    const int wc = wid & 3;      // 0..3

    FragC acc[4][2];
    #pragma unroll
    for (int i = 0; i < 4; i++)
        #pragma unroll
        for (int j = 0; j < 2; j++) wmma::fill_fragment(acc[i][j], 0.0f);

    LOAD_CHUNK(0, 0);
    CP_COMMIT();

    for (int kc = 0; kc < 16; kc++) {
        if (kc < 15) { LOAD_CHUNK(kc + 1, (kc + 1) & 1); CP_COMMIT(); CP_WAIT1(); }
        else         { CP_WAIT0(); }
        __syncthreads();

        const __nv_bfloat16* base = sm + (size_t)(kc & 1) * (4 * 128 * PITCH);
        const __nv_bfloat16* Ah = base;
        const __nv_bfloat16* Al = base + 128 * PITCH;
        const __nv_bfloat16* Bh = base + 2 * 128 * PITCH;
        const __nv_bfloat16* Bl = base + 3 * 128 * PITCH;

        #pragma unroll
        for (int kk = 0; kk < 4; kk++) {
            FragA ah[4], al[4];
            FragB bh[2], bl[2];
            #pragma unroll
            for (int i = 0; i < 4; i++) {
                int r = wn * 64 + i * 16;
                wmma::load_matrix_sync(ah[i], Ah + r * PITCH + kk * 16, PITCH);
                wmma::load_matrix_sync(al[i], Al + r * PITCH + kk * 16, PITCH);
            }
            #pragma unroll
            for (int j = 0; j < 2; j++) {
                int c = wc * 32 + j * 16;
                wmma::load_matrix_sync(bh[j], Bh + c * PITCH + kk * 16, PITCH);
                wmma::load_matrix_sync(bl[j], Bl + c * PITCH + kk * 16, PITCH);
            }
            #pragma unroll
            for (int i = 0; i < 4; i++)
                #pragma unroll
                for (int j = 0; j < 2; j++) {
                    wmma::mma_sync(acc[i][j], ah[i], bh[j], acc[i][j]);
                    wmma::mma_sync(acc[i][j], ah[i], bl[j], acc[i][j]);
                    wmma::mma_sync(acc[i][j], al[i], bh[j], acc[i][j]);
                }
        }
        __syncthreads();
    }

    #pragma unroll
    for (int i = 0; i < 4; i++) {
        const int row = n0 + wn * 64 + i * 16;
        #pragma unroll
        for (int j = 0; j < 2; j++) {
            const int col = c0 + wc * 32 + j * 16;
            wmma::store_matrix_sync(out + ((size_t)b * S + row) * D + col,
                                    acc[i][j], D, wmma::mem_row_major);
        }
    }
    #undef LOAD_CHUNK
}

// ---------------------------------------------------------------------------
extern "C" void kernel_launch(void* const* d_in, const int* in_sizes, int n_in,
                              void* d_out, int out_size)
{
    const float* x         = (const float*)d_in[0];
    const float* q_weight  = (const float*)d_in[1];
    const float* q_bias    = (const float*)d_in[2];
    const float* k_weight  = (const float*)d_in[3];
    const float* attn_bias = (const float*)d_in[4];

    float* out  = (float*)d_out;                       // [B,S,D]
    float* attn = (float*)d_out + (size_t)B * S * D;   // [B,S,S]

    cudaFuncSetAttribute(logits_mma, cudaFuncAttributeMaxDynamicSharedMemorySize, 73728);
    cudaFuncSetAttribute(out_mma,    cudaFuncAttributeMaxDynamicSharedMemorySize, 147456);

    proj_kernel<<<S, 256>>>(x, q_weight, q_bias, k_weight);

    xsplit_kernel<<<dim3(S / 32, D / 32, B), dim3(32, 8)>>>(x);

    logits_mma<<<1024, 256, 73728>>>(attn_bias, attn);

    softmax_kernel<<<B * S, 256>>>(attn);

    out_mma<<<384, 256, 147456>>>(out);
}